// round 2
// baseline (speedup 1.0000x reference)
#include <cuda_runtime.h>
#include <math.h>
#include <float.h>
#include <stdint.h>

#define L_    12
#define P_    100
#define B_    1024
#define D_    768
#define LP_   8
#define ROW_  (LP_*D_)   // 6144
#define TOPK  5
#define PPAD  128
#define BT    32         // batch tile (scores)
#define DC    32         // d chunk
#define CC    64         // col tile (output)
#define BTC   128        // batch tile (output)

// ---- device scratch (no allocations allowed) ----
__device__ float g_invK[L_*P_];
__device__ float g_coef[L_*P_];
__device__ float g_w  [L_*B_*TOPK];
__device__ int   g_idx[L_*B_*TOPK];

// =====================================================================
// Kernel A: per (l,p) — inverse K norm and coef = dot(l2norm(K),l2norm(A))
// =====================================================================
__global__ __launch_bounds__(128) void prep_kernel(const float* __restrict__ K_all,
                                                   const float* __restrict__ A_all) {
    int lp = blockIdx.x;                 // 0..1199
    const float* Kr = K_all + (size_t)lp * D_;
    const float* Ar = A_all + (size_t)lp * D_;
    float kk = 0.f, aa = 0.f, ka = 0.f;
    for (int i = threadIdx.x; i < D_; i += 128) {
        float k = Kr[i], a = Ar[i];
        kk = fmaf(k, k, kk);
        aa = fmaf(a, a, aa);
        ka = fmaf(k, a, ka);
    }
    #pragma unroll
    for (int o = 16; o; o >>= 1) {
        kk += __shfl_xor_sync(0xffffffffu, kk, o);
        aa += __shfl_xor_sync(0xffffffffu, aa, o);
        ka += __shfl_xor_sync(0xffffffffu, ka, o);
    }
    __shared__ float s[3][4];
    int w = threadIdx.x >> 5, ln = threadIdx.x & 31;
    if (ln == 0) { s[0][w] = kk; s[1][w] = aa; s[2][w] = ka; }
    __syncthreads();
    if (threadIdx.x == 0) {
        kk = s[0][0] + s[0][1] + s[0][2] + s[0][3];
        aa = s[1][0] + s[1][1] + s[1][2] + s[1][3];
        ka = s[2][0] + s[2][1] + s[2][2] + s[2][3];
        float ik = 1.f / fmaxf(sqrtf(kk), 1e-12f);
        float ia = 1.f / fmaxf(sqrtf(aa), 1e-12f);
        g_invK[lp] = ik;
        g_coef[lp] = ka * ik * ia;
    }
}

// =====================================================================
// Kernel B: scores GEMM (fp32) + top-5 per (l,b). Block = (l, 32 batches).
// Thread tile: 2 batches x 8 p (p = tx + 16*j to keep smem reads broadcast/
// conflict-free). Scores scaled by invK only (top-k invariant to |x| scale).
// =====================================================================
__global__ __launch_bounds__(256) void score_kernel(const float* __restrict__ x_query,
                                                    const float* __restrict__ K_all) {
    const int l  = blockIdx.y;
    const int b0 = blockIdx.x * BT;

    __shared__ float Ks[PPAD][DC + 1];   // [p][dd], pitch 33: conflict-free
    __shared__ float Xs[BT][DC + 4];     // [b][dd], pitch 36
    __shared__ float S [BT][PPAD];       // scores

    const int t  = threadIdx.x;
    const int tx = t & 15;               // p group
    const int ty = t >> 4;               // batch pair
    const int dp = (t & 7) << 2;         // loader: d offset (0..28)
    const int rr = t >> 3;               // loader: row 0..31

    float acc[2][8];
    #pragma unroll
    for (int i = 0; i < 2; ++i)
        #pragma unroll
        for (int j = 0; j < 8; ++j) acc[i][j] = 0.f;

    const float* xb = x_query + ((size_t)(b0 + rr) * L_ + l) * D_ + dp;
    const float* Kb = K_all   + (size_t)l * P_ * D_ + dp;

    for (int d0 = 0; d0 < D_; d0 += DC) {
        // -- load K chunk [128 x 32] layout [p][dd]
        #pragma unroll
        for (int pass = 0; pass < 4; ++pass) {
            int p = rr + (pass << 5);
            float4 kv = make_float4(0.f, 0.f, 0.f, 0.f);
            if (p < P_) kv = *(const float4*)(Kb + (size_t)p * D_ + d0);
            Ks[p][dp + 0] = kv.x; Ks[p][dp + 1] = kv.y;
            Ks[p][dp + 2] = kv.z; Ks[p][dp + 3] = kv.w;
        }
        // -- load X chunk [32 x 32]
        {
            float4 xv = *(const float4*)(xb + d0);
            Xs[rr][dp + 0] = xv.x; Xs[rr][dp + 1] = xv.y;
            Xs[rr][dp + 2] = xv.z; Xs[rr][dp + 3] = xv.w;
        }
        __syncthreads();

        #pragma unroll 8
        for (int dd = 0; dd < DC; ++dd) {
            float x0 = Xs[2 * ty + 0][dd];   // broadcast within warp
            float x1 = Xs[2 * ty + 1][dd];
            #pragma unroll
            for (int j = 0; j < 8; ++j) {
                float kv = Ks[tx + (j << 4)][dd];
                acc[0][j] = fmaf(x0, kv, acc[0][j]);
                acc[1][j] = fmaf(x1, kv, acc[1][j]);
            }
        }
        __syncthreads();
    }

    // -- scale by invK, pad lanes to -inf, dump to smem
    #pragma unroll
    for (int j = 0; j < 8; ++j) {
        int p = tx + (j << 4);
        float ik = (p < P_) ? g_invK[l * P_ + p] : 0.f;
        S[2 * ty + 0][p] = (p < P_) ? acc[0][j] * ik : -FLT_MAX;
        S[2 * ty + 1][p] = (p < P_) ? acc[1][j] * ik : -FLT_MAX;
    }
    __syncthreads();

    // -- top-5 per batch: 8 warps x 4 batches each
    const int w  = t >> 5;
    const int ln = t & 31;
    for (int bi = 0; bi < 4; ++bi) {
        int b = w + (bi << 3);           // 0..31
        float v[4];
        #pragma unroll
        for (int j = 0; j < 4; ++j) v[j] = S[b][ln + (j << 5)];
        int base = (l * B_ + b0 + b) * TOPK;
        #pragma unroll
        for (int k = 0; k < TOPK; ++k) {
            float bv = v[0]; int bj = 0;
            #pragma unroll
            for (int j = 1; j < 4; ++j) if (v[j] > bv) { bv = v[j]; bj = j; }
            int bidx = ln + (bj << 5);
            #pragma unroll
            for (int o = 16; o; o >>= 1) {
                float ov = __shfl_xor_sync(0xffffffffu, bv, o);
                int   oi = __shfl_xor_sync(0xffffffffu, bidx, o);
                if (ov > bv || (ov == bv && oi < bidx)) { bv = ov; bidx = oi; }
            }
            if (ln == 0) {
                g_idx[base + k] = bidx;
                g_w  [base + k] = g_coef[l * P_ + bidx];
            }
            if ((bidx & 31) == ln) v[bidx >> 5] = -FLT_MAX;
        }
    }
}

// =====================================================================
// Kernel C: OUT[l,b,:] = sum_k w[l,b,k] * P_all[l, idx[l,b,k], :]
// Block = (coltile 64, batchtile 128, l). All 100 P rows for this col
// slice staged in smem -> each row read once per (l,btile,coltile).
// =====================================================================
__global__ __launch_bounds__(256) void out_kernel(const float* __restrict__ P_all,
                                                  float* __restrict__ out) {
    const int l    = blockIdx.z;
    const int bt   = blockIdx.y;
    const int col0 = blockIdx.x * CC;

    __shared__ float Ps[P_][CC];        // 25.6 KB
    __shared__ float ws[BTC][TOPK];
    __shared__ int   is[BTC][TOPK];

    const int t = threadIdx.x;

    // FIXED (R1): grid-stride over all 640 (b,k) entries — previously only
    // the first 256 were staged, leaving is[b>=51][k] uninitialized garbage
    // that indexed shared memory out of bounds -> illegal memory access.
    for (int i = t; i < BTC * TOPK; i += 256) {
        int b = i / TOPK, k = i - b * TOPK;
        int gi = (l * B_ + bt * BTC + b) * TOPK + k;
        ws[b][k] = g_w[gi];
        is[b][k] = g_idx[gi];
    }
    const float* Pl = P_all + (size_t)l * P_ * ROW_ + col0;
    for (int i = t; i < P_ * (CC / 2); i += 256) {
        int p = i >> 5, c = i & 31;
        float2 v = *(const float2*)(Pl + (size_t)p * ROW_ + 2 * c);
        *(float2*)&Ps[p][2 * c] = v;
    }
    __syncthreads();

    const int w  = t >> 5;
    const int ln = t & 31;
    float* ob = out + (size_t)(l * B_ + bt * BTC) * ROW_ + col0 + 2 * ln;
    #pragma unroll 4
    for (int bb = 0; bb < 16; ++bb) {
        int b = w * 16 + bb;
        float w0 = ws[b][0], w1 = ws[b][1], w2 = ws[b][2], w3 = ws[b][3], w4 = ws[b][4];
        int   i0 = is[b][0], i1 = is[b][1], i2 = is[b][2], i3 = is[b][3], i4 = is[b][4];
        float2 p0 = *(const float2*)&Ps[i0][2 * ln];
        float2 p1 = *(const float2*)&Ps[i1][2 * ln];
        float2 p2 = *(const float2*)&Ps[i2][2 * ln];
        float2 p3 = *(const float2*)&Ps[i3][2 * ln];
        float2 p4 = *(const float2*)&Ps[i4][2 * ln];
        float2 o;
        o.x = fmaf(w4, p4.x, fmaf(w3, p3.x, fmaf(w2, p2.x, fmaf(w1, p1.x, w0 * p0.x))));
        o.y = fmaf(w4, p4.y, fmaf(w3, p3.y, fmaf(w2, p2.y, fmaf(w1, p1.y, w0 * p0.y))));
        *(float2*)(ob + (size_t)b * ROW_) = o;
    }
}

// =====================================================================
extern "C" void kernel_launch(void* const* d_in, const int* in_sizes, int n_in,
                              void* d_out, int out_size) {
    const float* x_query = (const float*)d_in[0];  // [B, L, D]
    const float* K_all   = (const float*)d_in[1];  // [L, P, D]
    const float* A_all   = (const float*)d_in[2];  // [L, P, D]
    const float* P_all   = (const float*)d_in[3];  // [L, P, Lp, D]
    float* out = (float*)d_out;                    // [L, B, Lp, D]
    (void)in_sizes; (void)n_in; (void)out_size;

    prep_kernel<<<L_ * P_, 128>>>(K_all, A_all);
    score_kernel<<<dim3(B_ / BT, L_), 256>>>(x_query, K_all);
    out_kernel<<<dim3(ROW_ / CC, B_ / BTC, L_), 256>>>(P_all, out);
}

// round 4
// speedup vs baseline: 1.1174x; 1.1174x over previous
#include <cuda_runtime.h>
#include <math.h>
#include <float.h>
#include <stdint.h>

#define L_    12
#define P_    100
#define B_    1024
#define D_    768
#define LP_   8
#define ROW_  (LP_*D_)   // 6144
#define TOPK  5
#define PP    112        // padded P (7 groups of 16)
#define BT    32         // batch tile (scores)
#define DC    32         // d chunk
#define KPITCH 34        // even pitch, bank stride 2 -> conflict-free float2
#define XPITCH 34
#define CC    64         // col tile (output)
#define BTC   128        // batch tile (output)

// ---- device scratch (no allocations allowed) ----
__device__ float g_invK[L_*P_];
__device__ float g_coef[L_*P_];
__device__ float g_w  [L_*B_*TOPK];
__device__ int   g_idx[L_*B_*TOPK];

// =====================================================================
// Kernel A: one warp per (l,p): invK and coef = dot(l2norm(K),l2norm(A))
// =====================================================================
__global__ __launch_bounds__(256) void prep_kernel(const float* __restrict__ K_all,
                                                   const float* __restrict__ A_all) {
    int gw = (blockIdx.x * 256 + threadIdx.x) >> 5;   // 0..1199
    int ln = threadIdx.x & 31;
    if (gw >= L_ * P_) return;
    const float* Kr = K_all + (size_t)gw * D_;
    const float* Ar = A_all + (size_t)gw * D_;
    float kk = 0.f, aa = 0.f, ka = 0.f;
    #pragma unroll
    for (int i = 0; i < 6; ++i) {
        float4 k = *(const float4*)(Kr + ((i << 5) + ln) * 4);
        float4 a = *(const float4*)(Ar + ((i << 5) + ln) * 4);
        kk = fmaf(k.x,k.x, fmaf(k.y,k.y, fmaf(k.z,k.z, fmaf(k.w,k.w, kk))));
        aa = fmaf(a.x,a.x, fmaf(a.y,a.y, fmaf(a.z,a.z, fmaf(a.w,a.w, aa))));
        ka = fmaf(k.x,a.x, fmaf(k.y,a.y, fmaf(k.z,a.z, fmaf(k.w,a.w, ka))));
    }
    #pragma unroll
    for (int o = 16; o; o >>= 1) {
        kk += __shfl_xor_sync(0xffffffffu, kk, o);
        aa += __shfl_xor_sync(0xffffffffu, aa, o);
        ka += __shfl_xor_sync(0xffffffffu, ka, o);
    }
    if (ln == 0) {
        float ik = 1.f / fmaxf(sqrtf(kk), 1e-12f);
        float ia = 1.f / fmaxf(sqrtf(aa), 1e-12f);
        g_invK[gw] = ik;
        g_coef[gw] = ka * ik * ia;
    }
}

// =====================================================================
// Kernel B: scores GEMM (fp32) + top-5.  Block = (l, 32 batches), 128 thr.
// Thread tile 4 batches x 7 p-groups (p = tx + 16*j, j<7 -> P pad 112).
// float2 operand loads; pitches even (bank stride 2) -> conflict-free.
// Scores scaled by invK only (top-k invariant to |x| scale; output does
// not depend on q at all except through the selected indices).
// =====================================================================
__global__ __launch_bounds__(128) void score_kernel(const float* __restrict__ x_query,
                                                    const float* __restrict__ K_all) {
    const int l  = blockIdx.y;
    const int b0 = blockIdx.x * BT;

    __shared__ __align__(16) float Ks[PP][KPITCH];   // 15.2 KB
    __shared__ __align__(16) float Xs[BT][XPITCH];   // 4.3 KB
    __shared__ __align__(16) float S [BT][128];      // 16 KB

    const int t   = threadIdx.x;
    const int tx  = t & 15;          // p group
    const int ty  = t >> 4;          // 0..7 -> batches 4*ty..4*ty+3
    const int ldp = (t & 7) << 2;    // loader d offset 0..28
    const int lr  = t >> 3;          // loader row 0..15

    float acc[4][7];
    #pragma unroll
    for (int i = 0; i < 4; ++i)
        #pragma unroll
        for (int j = 0; j < 7; ++j) acc[i][j] = 0.f;

    const float* Kb = K_all + (size_t)l * P_ * D_ + ldp;
    const float* xb = x_query + (size_t)l * D_ + ldp;

    for (int d0 = 0; d0 < D_; d0 += DC) {
        // K chunk: 112 rows x 32 d
        #pragma unroll
        for (int pass = 0; pass < 7; ++pass) {
            int p = lr + (pass << 4);
            float4 kv = make_float4(0.f, 0.f, 0.f, 0.f);
            if (p < P_) kv = *(const float4*)(Kb + (size_t)p * D_ + d0);
            Ks[p][ldp + 0] = kv.x; Ks[p][ldp + 1] = kv.y;
            Ks[p][ldp + 2] = kv.z; Ks[p][ldp + 3] = kv.w;
        }
        // X chunk: 32 rows x 32 d
        #pragma unroll
        for (int pass = 0; pass < 2; ++pass) {
            int b = lr + (pass << 4);
            float4 xv = *(const float4*)(xb + (size_t)(b0 + b) * (L_ * D_) + d0);
            Xs[b][ldp + 0] = xv.x; Xs[b][ldp + 1] = xv.y;
            Xs[b][ldp + 2] = xv.z; Xs[b][ldp + 3] = xv.w;
        }
        __syncthreads();

        #pragma unroll 8
        for (int dd = 0; dd < DC; dd += 2) {
            float2 kv[7], xv[4];
            #pragma unroll
            for (int j = 0; j < 7; ++j) kv[j] = *(const float2*)&Ks[tx + (j << 4)][dd];
            #pragma unroll
            for (int i = 0; i < 4; ++i) xv[i] = *(const float2*)&Xs[4 * ty + i][dd];
            #pragma unroll
            for (int i = 0; i < 4; ++i)
                #pragma unroll
                for (int j = 0; j < 7; ++j) {
                    acc[i][j] = fmaf(xv[i].x, kv[j].x, acc[i][j]);
                    acc[i][j] = fmaf(xv[i].y, kv[j].y, acc[i][j]);
                }
        }
        __syncthreads();
    }

    // scale by invK; fill pads with -inf
    #pragma unroll
    for (int j = 0; j < 8; ++j) {
        int p = tx + (j << 4);
        float ik = (p < P_) ? g_invK[l * P_ + p] : 0.f;
        #pragma unroll
        for (int i = 0; i < 4; ++i) {
            float v = (j < 7 && p < P_) ? acc[i][j] * ik : -FLT_MAX;
            S[4 * ty + i][p] = v;
        }
    }
    __syncthreads();

    // top-5 per batch: 4 warps x 8 batches
    const int w  = t >> 5;
    const int ln = t & 31;
    for (int bi = 0; bi < 8; ++bi) {
        int b = w + (bi << 2);           // 0..31
        float v[4];
        #pragma unroll
        for (int j = 0; j < 4; ++j) v[j] = S[b][ln + (j << 5)];
        int base = (l * B_ + b0 + b) * TOPK;
        #pragma unroll
        for (int k = 0; k < TOPK; ++k) {
            float bv = v[0]; int bj = 0;
            #pragma unroll
            for (int j = 1; j < 4; ++j) if (v[j] > bv) { bv = v[j]; bj = j; }
            int bidx = ln + (bj << 5);
            #pragma unroll
            for (int o = 16; o; o >>= 1) {
                float ov = __shfl_xor_sync(0xffffffffu, bv, o);
                int   oi = __shfl_xor_sync(0xffffffffu, bidx, o);
                if (ov > bv || (ov == bv && oi < bidx)) { bv = ov; bidx = oi; }
            }
            if (ln == 0) {
                g_idx[base + k] = bidx;
                g_w  [base + k] = g_coef[l * P_ + bidx];
            }
            if ((bidx & 31) == ln) v[bidx >> 5] = -FLT_MAX;
        }
    }
}

// =====================================================================
// Kernel C: OUT[l,b,:] = sum_k w[l,b,k] * P_all[l, idx[l,b,k], :]
// Block = (coltile 64, batchtile 128, l). All 100 P rows for this col
// slice staged in smem -> each row read once per (l,btile,coltile).
// =====================================================================
__global__ __launch_bounds__(256) void out_kernel(const float* __restrict__ P_all,
                                                  float* __restrict__ out) {
    const int l    = blockIdx.z;
    const int bt   = blockIdx.y;
    const int col0 = blockIdx.x * CC;

    __shared__ float Ps[P_][CC];        // 25.6 KB
    __shared__ float ws[BTC][TOPK];
    __shared__ int   is[BTC][TOPK];

    const int t = threadIdx.x;

    for (int i = t; i < BTC * TOPK; i += 256) {
        int b = i / TOPK, k = i - b * TOPK;
        int gi = (l * B_ + bt * BTC + b) * TOPK + k;
        ws[b][k] = g_w[gi];
        is[b][k] = g_idx[gi];
    }
    const float* Pl = P_all + (size_t)l * P_ * ROW_ + col0;
    for (int i = t; i < P_ * (CC / 2); i += 256) {
        int p = i >> 5, c = i & 31;
        float2 v = *(const float2*)(Pl + (size_t)p * ROW_ + 2 * c);
        *(float2*)&Ps[p][2 * c] = v;
    }
    __syncthreads();

    const int w  = t >> 5;
    const int ln = t & 31;
    float* ob = out + (size_t)(l * B_ + bt * BTC) * ROW_ + col0 + 2 * ln;
    #pragma unroll 4
    for (int bb = 0; bb < 16; ++bb) {
        int b = w * 16 + bb;
        float w0 = ws[b][0], w1 = ws[b][1], w2 = ws[b][2], w3 = ws[b][3], w4 = ws[b][4];
        int   i0 = is[b][0], i1 = is[b][1], i2 = is[b][2], i3 = is[b][3], i4 = is[b][4];
        float2 p0 = *(const float2*)&Ps[i0][2 * ln];
        float2 p1 = *(const float2*)&Ps[i1][2 * ln];
        float2 p2 = *(const float2*)&Ps[i2][2 * ln];
        float2 p3 = *(const float2*)&Ps[i3][2 * ln];
        float2 p4 = *(const float2*)&Ps[i4][2 * ln];
        float2 o;
        o.x = fmaf(w4, p4.x, fmaf(w3, p3.x, fmaf(w2, p2.x, fmaf(w1, p1.x, w0 * p0.x))));
        o.y = fmaf(w4, p4.y, fmaf(w3, p3.y, fmaf(w2, p2.y, fmaf(w1, p1.y, w0 * p0.y))));
        *(float2*)(ob + (size_t)b * ROW_) = o;
    }
}

// =====================================================================
extern "C" void kernel_launch(void* const* d_in, const int* in_sizes, int n_in,
                              void* d_out, int out_size) {
    const float* x_query = (const float*)d_in[0];  // [B, L, D]
    const float* K_all   = (const float*)d_in[1];  // [L, P, D]
    const float* A_all   = (const float*)d_in[2];  // [L, P, D]
    const float* P_all   = (const float*)d_in[3];  // [L, P, Lp, D]
    float* out = (float*)d_out;                    // [L, B, Lp, D]
    (void)in_sizes; (void)n_in; (void)out_size;

    prep_kernel<<<(L_ * P_ * 32 + 255) / 256, 256>>>(K_all, A_all);
    score_kernel<<<dim3(B_ / BT, L_), 128>>>(x_query, K_all);
    out_kernel<<<dim3(ROW_ / CC, B_ / BTC, L_), 256>>>(P_all, out);
}